// round 17
// baseline (speedup 1.0000x reference)
#include <cuda_runtime.h>
#include <cuda_bf16.h>
#include <math.h>
#include <cstdint>

// Problem constants
#define BATCH 2
#define SEQ 2048
#define DM 1024
#define NH 16
#define DH 64
#define MROWS (BATCH * SEQ)   // 4096

// ---------------------------------------------------------------------------
// Scratch (no cudaMalloc allowed)
// ---------------------------------------------------------------------------
__device__ __align__(256) float g_Q[MROWS * DM];
__device__ __align__(256) float g_K[MROWS * DM];
__device__ __align__(256) float g_V[MROWS * DM];
__device__ __align__(256) float g_C[MROWS * DM];

// ---------------------------------------------------------------------------
// Common helpers
// ---------------------------------------------------------------------------
__device__ __forceinline__ void mma_tf32(float& c0, float& c1, float& c2, float& c3,
                                         uint32_t a0, uint32_t a1, uint32_t a2, uint32_t a3,
                                         uint32_t b0, uint32_t b1) {
    asm volatile(
        "mma.sync.aligned.m16n8k8.row.col.f32.tf32.tf32.f32 "
        "{%0,%1,%2,%3}, {%4,%5,%6,%7}, {%8,%9}, {%0,%1,%2,%3};"
        : "+f"(c0), "+f"(c1), "+f"(c2), "+f"(c3)
        : "r"(a0), "r"(a1), "r"(a2), "r"(a3), "r"(b0), "r"(b1));
}

// fp32 -> tf32 round-to-nearest bit trick (HW truncates; +0x1000 completes RN)
__device__ __forceinline__ uint32_t rnd_tf32(uint32_t x) { return x + 0x1000u; }
__device__ __forceinline__ uint32_t rnd_tf32f(float x) { return __float_as_uint(x) + 0x1000u; }

__device__ __forceinline__ float ex2f(float x) {
    float y;
    asm("ex2.approx.f32 %0, %1;" : "=f"(y) : "f"(x));
    return y;
}

// ---------------------------------------------------------------------------
// tf32 mma.sync GEMM (unchanged R16 winner): C = A * W^T + bias
// CTA tile 128x256, 8 warps of 64x64, 1 CTA/SM (RF-capped), double-buffered
// BK=32, one barrier per chunk.
// ---------------------------------------------------------------------------
#define BM 128
#define BN 256
#define BK 32
#define KPAD 36
#define NCHUNK (DM / BK)
#define ABUF (BM * KPAD)
#define BBUF (BN * KPAD)
#define GEMM_SMEM_BYTES ((2 * ABUF + 2 * BBUF) * 4)   // 110592

__device__ __forceinline__ void gemm_body(
    const float* __restrict__ A, const float* __restrict__ W,
    const float* __restrict__ bias, float* __restrict__ C,
    int outmode, float oscale, uint32_t* gsm)
{
    uint32_t* As0 = gsm;
    uint32_t* Bs0 = gsm + 2 * ABUF;

    const int tid = threadIdx.x;
    const int wid = tid >> 5;
    const int lane = tid & 31;
    const int gid = lane >> 2;
    const int tig = lane & 3;

    const int wm = wid >> 2;
    const int wn = wid & 3;

    const int m0 = blockIdx.y * BM;
    const int n0 = blockIdx.x * BN;

    const int grow = tid >> 3;
    const int gcol = (tid & 7) * 4;

    const uint4* Ag = (const uint4*)(A + (long)(m0 + grow) * DM + gcol);
    const uint4* Wg = (const uint4*)(W + (long)(n0 + grow) * DM + gcol);

    float acc[4][8][4];
    #pragma unroll
    for (int i = 0; i < 4; i++)
        #pragma unroll
        for (int j = 0; j < 8; j++)
            #pragma unroll
            for (int c = 0; c < 4; c++) acc[i][j][c] = 0.0f;

    uint4 ra[4], rb[8];
    #pragma unroll
    for (int i = 0; i < 4; i++) ra[i] = Ag[(long)i * 32 * (DM / 4)];
    #pragma unroll
    for (int i = 0; i < 8; i++) rb[i] = Wg[(long)i * 32 * (DM / 4)];

    #pragma unroll
    for (int i = 0; i < 4; i++) {
        uint4 va = make_uint4(rnd_tf32(ra[i].x), rnd_tf32(ra[i].y),
                              rnd_tf32(ra[i].z), rnd_tf32(ra[i].w));
        *(uint4*)&As0[(grow + i * 32) * KPAD + gcol] = va;
    }
    #pragma unroll
    for (int i = 0; i < 8; i++) {
        uint4 vb = make_uint4(rnd_tf32(rb[i].x), rnd_tf32(rb[i].y),
                              rnd_tf32(rb[i].z), rnd_tf32(rb[i].w));
        *(uint4*)&Bs0[(grow + i * 32) * KPAD + gcol] = vb;
    }
    __syncthreads();

    for (int c = 0; c < NCHUNK; c++) {
        const uint32_t* As = As0 + (c & 1) * ABUF;
        const uint32_t* Bs = Bs0 + (c & 1) * BBUF;

        if (c + 1 < NCHUNK) {
            const uint4* an = Ag + (long)(c + 1) * (BK / 4);
            const uint4* bn = Wg + (long)(c + 1) * (BK / 4);
            #pragma unroll
            for (int i = 0; i < 4; i++) ra[i] = an[(long)i * 32 * (DM / 4)];
            #pragma unroll
            for (int i = 0; i < 8; i++) rb[i] = bn[(long)i * 32 * (DM / 4)];
        }

        #pragma unroll
        for (int ks = 0; ks < 4; ks++) {
            const int k0 = ks * 8;
            uint32_t af[4][4], bf[8][2];
            #pragma unroll
            for (int mt = 0; mt < 4; mt++) {
                const int r = wm * 64 + mt * 16 + gid;
                af[mt][0] = As[r * KPAD + k0 + tig];
                af[mt][1] = As[(r + 8) * KPAD + k0 + tig];
                af[mt][2] = As[r * KPAD + k0 + tig + 4];
                af[mt][3] = As[(r + 8) * KPAD + k0 + tig + 4];
            }
            #pragma unroll
            for (int nt = 0; nt < 8; nt++) {
                const int r = wn * 64 + nt * 8 + gid;
                bf[nt][0] = Bs[r * KPAD + k0 + tig];
                bf[nt][1] = Bs[r * KPAD + k0 + tig + 4];
            }
            #pragma unroll
            for (int mt = 0; mt < 4; mt++)
                #pragma unroll
                for (int nt = 0; nt < 8; nt++)
                    mma_tf32(acc[mt][nt][0], acc[mt][nt][1],
                             acc[mt][nt][2], acc[mt][nt][3],
                             af[mt][0], af[mt][1], af[mt][2], af[mt][3],
                             bf[nt][0], bf[nt][1]);
        }

        if (c + 1 < NCHUNK) {
            uint32_t* An = As0 + ((c + 1) & 1) * ABUF;
            uint32_t* Bn = Bs0 + ((c + 1) & 1) * BBUF;
            #pragma unroll
            for (int i = 0; i < 4; i++) {
                uint4 va = make_uint4(rnd_tf32(ra[i].x), rnd_tf32(ra[i].y),
                                      rnd_tf32(ra[i].z), rnd_tf32(ra[i].w));
                *(uint4*)&An[(grow + i * 32) * KPAD + gcol] = va;
            }
            #pragma unroll
            for (int i = 0; i < 8; i++) {
                uint4 vb = make_uint4(rnd_tf32(rb[i].x), rnd_tf32(rb[i].y),
                                      rnd_tf32(rb[i].z), rnd_tf32(rb[i].w));
                *(uint4*)&Bn[(grow + i * 32) * KPAD + gcol] = vb;
            }
        }
        __syncthreads();
    }

    #pragma unroll
    for (int mt = 0; mt < 4; mt++) {
        const int mrow = m0 + wm * 64 + mt * 16 + gid;
        #pragma unroll
        for (int nt = 0; nt < 8; nt++) {
            const int ncol = n0 + wn * 64 + nt * 8 + tig * 2;
            const float bx = bias[ncol];
            const float by = bias[ncol + 1];
            float v00 = acc[mt][nt][0] + bx, v01 = acc[mt][nt][1] + by;
            float v10 = acc[mt][nt][2] + bx, v11 = acc[mt][nt][3] + by;
            float2 w0, w1;
            if (outmode == 1) {
                w0 = make_float2(__uint_as_float(rnd_tf32f(v00 * oscale)),
                                 __uint_as_float(rnd_tf32f(v01 * oscale)));
                w1 = make_float2(__uint_as_float(rnd_tf32f(v10 * oscale)),
                                 __uint_as_float(rnd_tf32f(v11 * oscale)));
            } else {
                w0 = make_float2(v00, v01);
                w1 = make_float2(v10, v11);
            }
            *(float2*)(C + (long)mrow * DM + ncol) = w0;
            *(float2*)(C + (long)(mrow + 8) * DM + ncol) = w1;
        }
    }
}

// Merged QKV projection: blockIdx.z selects (input, W, bias, output, scale).
__global__ __launch_bounds__(256) void qkv_gemm_kernel(
    const float* __restrict__ q, const float* __restrict__ k,
    const float* __restrict__ v,
    const float* __restrict__ Wq, const float* __restrict__ bq,
    const float* __restrict__ Wk, const float* __restrict__ bk,
    const float* __restrict__ Wv, const float* __restrict__ bv,
    float* __restrict__ oQ, float* __restrict__ oK, float* __restrict__ oV,
    float qscale)
{
    extern __shared__ uint32_t gsm[];
    const int z = blockIdx.z;
    const float* A    = (z == 0) ? q  : (z == 1) ? k  : v;
    const float* W    = (z == 0) ? Wq : (z == 1) ? Wk : Wv;
    const float* bias = (z == 0) ? bq : (z == 1) ? bk : bv;
    float*       C    = (z == 0) ? oQ : (z == 1) ? oK : oV;
    const float os    = (z == 0) ? qscale : 1.0f;
    gemm_body(A, W, bias, C, 1, os, gsm);
}

// Output projection (exact fp32 epilogue).
__global__ __launch_bounds__(256) void gemm_tf32_kernel(
    const float* __restrict__ A, const float* __restrict__ W,
    const float* __restrict__ bias, float* __restrict__ C)
{
    extern __shared__ uint32_t gsm[];
    gemm_body(A, W, bias, C, 0, 1.0f, gsm);
}

// ---------------------------------------------------------------------------
// Tensor-core flash attention — fine-grained CTA version.
// 128 threads (4 warps x 16 q-rows = 64 q-rows/CTA), 64-key tiles,
// 4 CTAs/SM (RF: 128 regs x 128 thr x 4 = 64K exactly; smem 52.2 KB/CTA).
// Same per-thread math frame as R6/R15 -> bit-identical numerics.
// 3 other independent CTAs absorb each CTA's barrier/softmax stalls.
// V^T XOR-swizzled (CF store + CF read), P via smem roundtrip,
// inputs pre-rounded (Q pre-scaled) by the projection GEMMs.
// ---------------------------------------------------------------------------
#define APAD 68
#define ATT_SMEM_U32 (3 * 64 * APAD)      // Ps + Ks + Vt, each [64][68]
#define ATT_SMEM_BYTES (ATT_SMEM_U32 * 4) // 52224

__global__ __launch_bounds__(128, 4) void attn_mma_kernel(
    const float* __restrict__ Q, const float* __restrict__ K,
    const float* __restrict__ V, float* __restrict__ Ctx)
{
    extern __shared__ uint32_t sm[];
    uint32_t* Ps = sm;                    // [64][APAD]  Q stage + P roundtrip
    uint32_t* Ks = sm + 64 * APAD;        // [64][APAD]  K[key][dh]
    uint32_t* Vt = Ks + 64 * APAD;        // [64][APAD]  V^T[dh][key-swizzled]

    const int bh = blockIdx.y;
    const int b  = bh >> 4;
    const int h  = bh & 15;
    const int q0 = blockIdx.x * 64;

    const int tid  = threadIdx.x;
    const int wid  = tid >> 5;            // 0..3
    const int lane = tid & 31;
    const int gid  = lane >> 2;
    const int tig  = lane & 3;
    const int r0   = wid * 16 + gid;      // this thread's first q-row (0..63)

    const float* Qg = Q + ((long)b * SEQ) * DM + h * DH;
    const float* Kg = K + ((long)b * SEQ) * DM + h * DH;
    const float* Vg = V + ((long)b * SEQ) * DM + h * DH;

    // staging coords (coalesced): 4 threads per key row, 16 dh floats each;
    // 128 threads cover 32 key rows per batch -> 2 batches for 64 keys.
    const int krow = tid >> 2;            // 0..31
    const int kc   = (tid & 3) * 16;      // 0,16,32,48
    const int vxor = (kc >> 4) << 3;      // 8*(dh>>4), constant per thread

    // ---- stage Q (pre-scaled, pre-rounded): pure copy, 64 rows
    {
        const int row  = tid >> 1;        // 0..63
        const int col0 = (tid & 1) * 32;
        const uint4* qp = (const uint4*)(Qg + (long)(q0 + row) * DM + col0);
        #pragma unroll
        for (int j = 0; j < 8; j++)
            *(uint4*)&Ps[row * APAD + col0 + j * 4] = qp[j];
    }
    __syncthreads();

    // ---- persistent Q fragments
    uint32_t qf[8][4];
    #pragma unroll
    for (int ks = 0; ks < 8; ks++) {
        qf[ks][0] = Ps[r0 * APAD + ks * 8 + tig];
        qf[ks][1] = Ps[(r0 + 8) * APAD + ks * 8 + tig];
        qf[ks][2] = Ps[r0 * APAD + ks * 8 + tig + 4];
        qf[ks][3] = Ps[(r0 + 8) * APAD + ks * 8 + tig + 4];
    }

    float o[8][4];
    #pragma unroll
    for (int nt = 0; nt < 8; nt++)
        #pragma unroll
        for (int c = 0; c < 4; c++) o[nt][c] = 0.0f;
    float mr0 = -INFINITY, mr1 = -INFINITY, l0 = 0.0f, l1 = 0.0f;

    const int NT = SEQ / 64;   // 32 key tiles
    for (int it = 0; it < NT; it++) {
        __syncthreads();   // prior-tile fragment reads complete

        // ---- stage 64 keys: K[key][dh] + swizzled V^T[dh][key], 2 batches
        #pragma unroll
        for (int batch = 0; batch < 2; batch++) {
            const int keyl = batch * 32 + krow;
            const long kr  = (long)(it * 64 + keyl);
            const uint4* kp = (const uint4*)(Kg + kr * DM + kc);
            const uint4* vp = (const uint4*)(Vg + kr * DM + kc);
            const int vcol = keyl ^ vxor;
            #pragma unroll
            for (int j = 0; j < 4; j++) {
                *(uint4*)&Ks[keyl * APAD + kc + 4 * j] = kp[j];
                uint4 vv = vp[j];
                const int dv = kc + 4 * j;
                Vt[(dv + 0) * APAD + vcol] = vv.x;
                Vt[(dv + 1) * APAD + vcol] = vv.y;
                Vt[(dv + 2) * APAD + vcol] = vv.z;
                Vt[(dv + 3) * APAD + vcol] = vv.w;
            }
        }
        __syncthreads();

        // ---- S = Q * K^T  (per warp: 16 x 64)
        float s[8][4];
        #pragma unroll
        for (int nt = 0; nt < 8; nt++)
            #pragma unroll
            for (int c = 0; c < 4; c++) s[nt][c] = 0.0f;

        #pragma unroll
        for (int nt = 0; nt < 8; nt++) {
            const uint32_t* kb = &Ks[(nt * 8 + gid) * APAD];
            #pragma unroll
            for (int ks = 0; ks < 8; ks++) {
                uint32_t b0 = kb[ks * 8 + tig];
                uint32_t b1 = kb[ks * 8 + tig + 4];
                mma_tf32(s[nt][0], s[nt][1], s[nt][2], s[nt][3],
                         qf[ks][0], qf[ks][1], qf[ks][2], qf[ks][3], b0, b1);
            }
        }

        // ---- online softmax (log2 domain)
        float mt0 = -INFINITY, mt1 = -INFINITY;
        #pragma unroll
        for (int nt = 0; nt < 8; nt++) {
            mt0 = fmaxf(mt0, fmaxf(s[nt][0], s[nt][1]));
            mt1 = fmaxf(mt1, fmaxf(s[nt][2], s[nt][3]));
        }
        mt0 = fmaxf(mt0, __shfl_xor_sync(0xffffffffu, mt0, 1));
        mt0 = fmaxf(mt0, __shfl_xor_sync(0xffffffffu, mt0, 2));
        mt1 = fmaxf(mt1, __shfl_xor_sync(0xffffffffu, mt1, 1));
        mt1 = fmaxf(mt1, __shfl_xor_sync(0xffffffffu, mt1, 2));

        const float mn0 = fmaxf(mr0, mt0);
        const float mn1 = fmaxf(mr1, mt1);
        const float a0 = ex2f(mr0 - mn0);
        const float a1 = ex2f(mr1 - mn1);
        mr0 = mn0; mr1 = mn1;

        float rs0 = 0.0f, rs1 = 0.0f;
        #pragma unroll
        for (int nt = 0; nt < 8; nt++) {
            float p0 = ex2f(s[nt][0] - mn0);
            float p1 = ex2f(s[nt][1] - mn0);
            float p2 = ex2f(s[nt][2] - mn1);
            float p3 = ex2f(s[nt][3] - mn1);
            rs0 += p0 + p1;
            rs1 += p2 + p3;
            uint2 w0 = make_uint2(rnd_tf32f(p0), rnd_tf32f(p1));
            uint2 w1 = make_uint2(rnd_tf32f(p2), rnd_tf32f(p3));
            *(uint2*)&Ps[r0 * APAD + nt * 8 + tig * 2] = w0;
            *(uint2*)&Ps[(r0 + 8) * APAD + nt * 8 + tig * 2] = w1;
        }
        rs0 += __shfl_xor_sync(0xffffffffu, rs0, 1);
        rs0 += __shfl_xor_sync(0xffffffffu, rs0, 2);
        rs1 += __shfl_xor_sync(0xffffffffu, rs1, 1);
        rs1 += __shfl_xor_sync(0xffffffffu, rs1, 2);

        l0 = l0 * a0 + rs0;
        l1 = l1 * a1 + rs1;
        #pragma unroll
        for (int nt = 0; nt < 8; nt++) {
            o[nt][0] *= a0; o[nt][1] *= a0;
            o[nt][2] *= a1; o[nt][3] *= a1;
        }
        __syncwarp();   // P stores visible to all lanes of this warp

        // ---- O += P * V  (swizzled V^T reads, CF)
        #pragma unroll
        for (int ks = 0; ks < 8; ks++) {
            uint32_t pa0 = Ps[r0 * APAD + ks * 8 + tig];
            uint32_t pa1 = Ps[(r0 + 8) * APAD + ks * 8 + tig];
            uint32_t pa2 = Ps[r0 * APAD + ks * 8 + tig + 4];
            uint32_t pa3 = Ps[(r0 + 8) * APAD + ks * 8 + tig + 4];
            #pragma unroll
            for (int nt = 0; nt < 8; nt++) {
                const uint32_t* vb = &Vt[(nt * 8 + gid) * APAD];
                const int ci = (ks * 8 + tig) ^ ((nt >> 1) << 3);
                uint32_t b0 = vb[ci];
                uint32_t b1 = vb[ci + 4];
                mma_tf32(o[nt][0], o[nt][1], o[nt][2], o[nt][3],
                         pa0, pa1, pa2, pa3, b0, b1);
            }
        }
        __syncwarp();   // PV reads of Ps done before next tile's P overwrites
    }

    // ---- epilogue: normalize and write context
    const float inv0 = 1.0f / l0;
    const float inv1 = 1.0f / l1;
    float* C0 = Ctx + ((long)b * SEQ + q0 + r0) * DM + h * DH;
    float* C1 = Ctx + ((long)b * SEQ + q0 + r0 + 8) * DM + h * DH;
    #pragma unroll
    for (int nt = 0; nt < 8; nt++) {
        const int col = nt * 8 + tig * 2;
        *(float2*)(C0 + col) = make_float2(o[nt][0] * inv0, o[nt][1] * inv0);
        *(float2*)(C1 + col) = make_float2(o[nt][2] * inv1, o[nt][3] * inv1);
    }
}

// ---------------------------------------------------------------------------
// kernel_launch  — inputs: q,k,v, Wq,bq, Wk,bk, Wv,bv, Wo,bo
// ---------------------------------------------------------------------------
extern "C" void kernel_launch(void* const* d_in, const int* in_sizes, int n_in,
                              void* d_out, int out_size)
{
    const float* q  = (const float*)d_in[0];
    const float* k  = (const float*)d_in[1];
    const float* v  = (const float*)d_in[2];
    const float* Wq = (const float*)d_in[3];
    const float* bq = (const float*)d_in[4];
    const float* Wk = (const float*)d_in[5];
    const float* bk = (const float*)d_in[6];
    const float* Wv = (const float*)d_in[7];
    const float* bv = (const float*)d_in[8];
    const float* Wo = (const float*)d_in[9];
    const float* bo = (const float*)d_in[10];
    float* out = (float*)d_out;

    float *pQ, *pK, *pV, *pC;
    cudaGetSymbolAddress((void**)&pQ, g_Q);
    cudaGetSymbolAddress((void**)&pK, g_K);
    cudaGetSymbolAddress((void**)&pV, g_V);
    cudaGetSymbolAddress((void**)&pC, g_C);

    cudaFuncSetAttribute(qkv_gemm_kernel,
                         cudaFuncAttributeMaxDynamicSharedMemorySize,
                         GEMM_SMEM_BYTES);
    cudaFuncSetAttribute(gemm_tf32_kernel,
                         cudaFuncAttributeMaxDynamicSharedMemorySize,
                         GEMM_SMEM_BYTES);
    cudaFuncSetAttribute(attn_mma_kernel,
                         cudaFuncAttributeMaxDynamicSharedMemorySize,
                         ATT_SMEM_BYTES);

    const float cf = 0.125f * 1.44269504088896f;   // 1/sqrt(64) * log2(e)

    // merged Q/K/V projections (pre-rounded tf32 outputs; Q pre-scaled)
    dim3 qkvgrid(DM / BN, MROWS / BM, 3);   // (4, 32, 3)
    qkv_gemm_kernel<<<qkvgrid, 256, GEMM_SMEM_BYTES>>>(
        q, k, v, Wq, bq, Wk, bk, Wv, bv, pQ, pK, pV, cf);

    dim3 agrid(SEQ / 64, BATCH * NH);       // (32, 32) = 1024 CTAs
    attn_mma_kernel<<<agrid, 128, ATT_SMEM_BYTES>>>(pQ, pK, pV, pC);

    // final projection: exact fp32 output
    dim3 ggrid(DM / BN, MROWS / BM);        // (4, 32)
    gemm_tf32_kernel<<<ggrid, 256, GEMM_SMEM_BYTES>>>(pC, Wo, bo, out);
}